// round 1
// baseline (speedup 1.0000x reference)
#include <cuda_runtime.h>
#include <math_constants.h>

#define BB 4
#define NN 2048
#define DD 1024
#define HH 64
#define SCALE 0.125f  /* H^-0.5 */

// Scratch (allocation-free rule: __device__ globals)
__device__ float g_q[BB * NN * HH];
__device__ float g_k[BB * NN * HH];
__device__ float g_v[BB * NN * HH];
__device__ float g_s[(size_t)BB * NN * NN];  // scores, then attn (in place)

// ---------------------------------------------------------------------------
// K1: q/k/v = x @ W + b.   grid (M/64, 3), 256 threads, 64x64 tile, BK=32.
// ---------------------------------------------------------------------------
__global__ void qkv_kernel(const float* __restrict__ x,
                           const float* __restrict__ Wq, const float* __restrict__ bq,
                           const float* __restrict__ Wk, const float* __restrict__ bk,
                           const float* __restrict__ Wv, const float* __restrict__ bv) {
    const int proj = blockIdx.y;
    const float* W    = proj == 0 ? Wq : (proj == 1 ? Wk : Wv);
    const float* bias = proj == 0 ? bq : (proj == 1 ? bk : bv);
    float* out        = proj == 0 ? g_q : (proj == 1 ? g_k : g_v);

    __shared__ float As[64][33];  // [m][k]
    __shared__ float Bs[32][65];  // [k][n]

    const int m0  = blockIdx.x * 64;
    const int tid = threadIdx.x;
    const int tr  = tid >> 4;     // 0..15 (row group)
    const int tc  = tid & 15;     // 0..15 (col group)

    float acc[4][4] = {};

    for (int k0 = 0; k0 < DD; k0 += 32) {
        #pragma unroll
        for (int l = 0; l < 8; l++) {
            int idx = tid + l * 256;            // 0..2047
            int r = idx >> 5, c = idx & 31;
            As[r][c] = x[(size_t)(m0 + r) * DD + k0 + c];
        }
        #pragma unroll
        for (int l = 0; l < 8; l++) {
            int idx = tid + l * 256;
            int r = idx >> 6, c = idx & 63;
            Bs[r][c] = W[(size_t)(k0 + r) * HH + c];
        }
        __syncthreads();

        #pragma unroll
        for (int kk = 0; kk < 32; kk++) {
            float a[4], b[4];
            #pragma unroll
            for (int i = 0; i < 4; i++) a[i] = As[tr * 4 + i][kk];
            #pragma unroll
            for (int j = 0; j < 4; j++) b[j] = Bs[kk][tc * 4 + j];
            #pragma unroll
            for (int i = 0; i < 4; i++)
                #pragma unroll
                for (int j = 0; j < 4; j++)
                    acc[i][j] += a[i] * b[j];
        }
        __syncthreads();
    }

    #pragma unroll
    for (int i = 0; i < 4; i++) {
        int r = m0 + tr * 4 + i;
        #pragma unroll
        for (int j = 0; j < 4; j++) {
            int c = tc * 4 + j;
            out[(size_t)r * HH + c] = acc[i][j] + bias[c];
        }
    }
}

// ---------------------------------------------------------------------------
// K2: scores[b][j][i] = q[b,j]·k[b,i], masked (keep i>=j and s!=0) and scaled.
// grid (32 i-tiles, 32 j-tiles, B). Tiles fully below the kept triangle skip.
// ---------------------------------------------------------------------------
__global__ void scores_kernel() {
    const int it = blockIdx.x, jt = blockIdx.y, b = blockIdx.z;
    if (it < jt) return;  // entire tile has i < j -> handled as -inf in softmax

    __shared__ float Qs[64][65];  // [j][d]
    __shared__ float Ks[64][65];  // [i][d]

    const int i0 = it * 64, j0 = jt * 64;
    const int tid = threadIdx.x;
    const float* qb = g_q + (size_t)b * NN * HH;
    const float* kb = g_k + (size_t)b * NN * HH;

    #pragma unroll
    for (int l = 0; l < 16; l++) {
        int idx = tid + l * 256;
        int r = idx >> 6, c = idx & 63;
        Qs[r][c] = qb[(size_t)(j0 + r) * HH + c];
        Ks[r][c] = kb[(size_t)(i0 + r) * HH + c];
    }
    __syncthreads();

    const int tr = tid >> 4;  // j group
    const int tc = tid & 15;  // i group
    float acc[4][4] = {};

    #pragma unroll
    for (int d = 0; d < 64; d++) {
        float a[4], c4[4];
        #pragma unroll
        for (int i = 0; i < 4; i++) a[i] = Qs[tr * 4 + i][d];
        #pragma unroll
        for (int j = 0; j < 4; j++) c4[j] = Ks[tc * 4 + j][d];
        #pragma unroll
        for (int i = 0; i < 4; i++)
            #pragma unroll
            for (int j = 0; j < 4; j++)
                acc[i][j] += a[i] * c4[j];
    }

    float* sb = g_s + (size_t)b * NN * NN;
    #pragma unroll
    for (int i = 0; i < 4; i++) {
        int jj = j0 + tr * 4 + i;  // row
        #pragma unroll
        for (int j = 0; j < 4; j++) {
            int ii = i0 + tc * 4 + j;  // col
            float s = acc[i][j];
            // faithful to ref: triu keeps col>=row, then exact zeros -> -inf,
            // then multiply by scale (scale of -inf stays -inf).
            float v = (ii >= jj && s != 0.0f) ? s * SCALE : -CUDART_INF_F;
            sb[(size_t)jj * NN + ii] = v;
        }
    }
}

// ---------------------------------------------------------------------------
// K3: row softmax over i (axis=-1). One 256-thread block per (b,j) row.
// Entries i<j synthesized as -inf (never written by K2); writes attn=0 there.
// ---------------------------------------------------------------------------
__global__ void softmax_kernel() {
    const int row = blockIdx.x;         // 0 .. B*N-1
    const int b = row >> 11;            // /2048
    const int j = row & (NN - 1);
    float* srow = g_s + (size_t)b * NN * NN + (size_t)j * NN;

    const int tid = threadIdx.x;  // 256
    float vals[8];
    float m = -CUDART_INF_F;

    #pragma unroll
    for (int l = 0; l < 8; l++) {
        int ii = tid + l * 256;
        float v = (ii >= j) ? srow[ii] : -CUDART_INF_F;
        vals[l] = v;
        m = fmaxf(m, v);
    }

    __shared__ float red[8];
    #pragma unroll
    for (int o = 16; o > 0; o >>= 1) m = fmaxf(m, __shfl_xor_sync(0xffffffffu, m, o));
    if ((tid & 31) == 0) red[tid >> 5] = m;
    __syncthreads();
    float mt = red[0];
    #pragma unroll
    for (int w = 1; w < 8; w++) mt = fmaxf(mt, red[w]);

    float sum = 0.0f;
    #pragma unroll
    for (int l = 0; l < 8; l++) {
        float e = __expf(vals[l] - mt);  // exp(-inf - m) = 0
        vals[l] = e;
        sum += e;
    }
    #pragma unroll
    for (int o = 16; o > 0; o >>= 1) sum += __shfl_xor_sync(0xffffffffu, sum, o);
    __syncthreads();
    if ((tid & 31) == 0) red[tid >> 5] = sum;
    __syncthreads();
    float st = 0.0f;
    #pragma unroll
    for (int w = 0; w < 8; w++) st += red[w];

    float inv = 1.0f / st;
    #pragma unroll
    for (int l = 0; l < 8; l++) srow[tid + l * 256] = vals[l] * inv;
}

// ---------------------------------------------------------------------------
// K4: out[b,i,h] = sum_j attn[b,j,i] * v[b,j,h]   (transposed application!)
// attn[j,i]==0 for j>i, so only j-tiles <= i-tile contribute.
// grid (32 i-tiles, B), 256 threads, 64(i) x 64(h) tile.
// ---------------------------------------------------------------------------
__global__ void out_kernel(float* __restrict__ out) {
    const int it = blockIdx.x, b = blockIdx.y;
    const int i0 = it * 64;

    __shared__ float As[64][65];  // [j][i]
    __shared__ float Vs[64][65];  // [j][h]

    const int tid = threadIdx.x;
    const int tr = tid >> 4;  // i group
    const int tc = tid & 15;  // h group
    float acc[4][4] = {};

    const float* ab = g_s + (size_t)b * NN * NN;
    const float* vb = g_v + (size_t)b * NN * HH;

    for (int jt = 0; jt <= it; jt++) {
        int j0 = jt * 64;
        #pragma unroll
        for (int l = 0; l < 16; l++) {
            int idx = tid + l * 256;
            int r = idx >> 6, c = idx & 63;
            As[r][c] = ab[(size_t)(j0 + r) * NN + i0 + c];
            Vs[r][c] = vb[(size_t)(j0 + r) * HH + c];
        }
        __syncthreads();

        #pragma unroll
        for (int jj = 0; jj < 64; jj++) {
            float a[4], v4[4];
            #pragma unroll
            for (int i = 0; i < 4; i++) a[i] = As[jj][tr * 4 + i];
            #pragma unroll
            for (int h = 0; h < 4; h++) v4[h] = Vs[jj][tc * 4 + h];
            #pragma unroll
            for (int i = 0; i < 4; i++)
                #pragma unroll
                for (int h = 0; h < 4; h++)
                    acc[i][h] += a[i] * v4[h];
        }
        __syncthreads();
    }

    #pragma unroll
    for (int i = 0; i < 4; i++)
        #pragma unroll
        for (int h = 0; h < 4; h++)
            out[(size_t)b * NN * HH + (size_t)(i0 + tr * 4 + i) * HH + tc * 4 + h] =
                acc[i][h];
}

// ---------------------------------------------------------------------------
extern "C" void kernel_launch(void* const* d_in, const int* in_sizes, int n_in,
                              void* d_out, int out_size) {
    const float* x  = (const float*)d_in[0];
    const float* Wq = (const float*)d_in[1];
    const float* bq = (const float*)d_in[2];
    const float* Wk = (const float*)d_in[3];
    const float* bk = (const float*)d_in[4];
    const float* Wv = (const float*)d_in[5];
    const float* bv = (const float*)d_in[6];
    float* out = (float*)d_out;

    dim3 g1((BB * NN) / 64, 3);
    qkv_kernel<<<g1, 256>>>(x, Wq, bq, Wk, bk, Wv, bv);

    dim3 g2(NN / 64, NN / 64, BB);
    scores_kernel<<<g2, 256>>>();

    softmax_kernel<<<BB * NN, 256>>>();

    dim3 g4(NN / 64, BB);
    out_kernel<<<g4, 256>>>(out);
}

// round 4
// speedup vs baseline: 1.4441x; 1.4441x over previous
#include <cuda_runtime.h>
#include <math_constants.h>

#define BB 4
#define NN 2048
#define DD 1024
#define HH 64
#define SCALE 0.125f /* H^-0.5 */

typedef unsigned long long ull;

// Scratch (allocation-free rule: __device__ globals)
__device__ float g_q[BB * NN * HH];
__device__ float g_k[BB * NN * HH];
__device__ float g_v[BB * NN * HH];
__device__ float g_s[(size_t)BB * NN * NN];  // scores, then attn (in place)

// ---- packed f32x2 helpers (FFMA2: 2 fp32 FMAs per issue slot) ------------
__device__ __forceinline__ ull pk2(float lo, float hi) {
    ull r; asm("mov.b64 %0, {%1, %2};" : "=l"(r) : "f"(lo), "f"(hi)); return r;
}
__device__ __forceinline__ void upk2(ull v, float& lo, float& hi) {
    asm("mov.b64 {%0, %1}, %2;" : "=f"(lo), "=f"(hi) : "l"(v));
}
__device__ __forceinline__ void fma2(ull& d, ull a, ull b) {
    asm("fma.rn.f32x2 %0, %1, %2, %0;" : "+l"(d) : "l"(a), "l"(b));
}

// ---------------------------------------------------------------------------
// K0: zero g_q/g_k/g_v and out (they are accumulated via atomics).
// grid 512 x 256 threads, one float4 per array per thread.
// ---------------------------------------------------------------------------
__global__ void zero_kernel(float* __restrict__ out) {
    int idx = blockIdx.x * 256 + threadIdx.x;  // 0..131071 (=BB*NN*HH/4)
    float4 z = make_float4(0.f, 0.f, 0.f, 0.f);
    *(float4*)&g_q[idx * 4] = z;
    *(float4*)&g_k[idx * 4] = z;
    *(float4*)&g_v[idx * 4] = z;
    *(float4*)&out[idx * 4] = z;
}

// ---------------------------------------------------------------------------
// K1: q/k/v = x @ W + b.  Tile 128 rows x 64 cols, BK=32, split-K=2 (atomic).
// grid (64, 2, 3), 256 threads. Per thread: 8 rows x 4 cols, FFMA2 pairs
// along rows. a-frag = smem broadcast; b-frag = float4, 2-phase.
// ---------------------------------------------------------------------------
__global__ __launch_bounds__(256, 2)
void qkv_kernel(const float* __restrict__ x,
                const float* __restrict__ Wq, const float* __restrict__ bq,
                const float* __restrict__ Wk, const float* __restrict__ bk,
                const float* __restrict__ Wv, const float* __restrict__ bv) {
    const int proj = blockIdx.z;
    const int ks   = blockIdx.y;          // k-half: [ks*512, ks*512+512)
    const float* W    = proj == 0 ? Wq : (proj == 1 ? Wk : Wv);
    const float* bias = proj == 0 ? bq : (proj == 1 ? bk : bv);
    float* out        = proj == 0 ? g_q : (proj == 1 ? g_k : g_v);

    __shared__ __align__(16) float Xs[128][32];
    __shared__ __align__(16) float Ws[32][64];

    const int m0  = blockIdx.x * 128;
    const int tid = threadIdx.x;
    const int tr  = tid >> 4;   // 0..15
    const int tc  = tid & 15;   // 0..15

    ull acc[4][4] = {};  // [row-pair][col]; pair p holds rows (tr+32p, tr+32p+16)

    const int kbeg = ks * 512, kend = kbeg + 512;
    for (int k0 = kbeg; k0 < kend; k0 += 32) {
        #pragma unroll
        for (int l = 0; l < 4; l++) {
            int idx = tid + l * 256;       // 1024 float4 slots
            int r = idx >> 3, c4 = idx & 7;
            *(float4*)&Xs[r][c4 * 4] =
                *(const float4*)&x[(size_t)(m0 + r) * DD + k0 + c4 * 4];
        }
        #pragma unroll
        for (int l = 0; l < 2; l++) {
            int idx = tid + l * 256;       // 512 float4 slots
            int r = idx >> 4, c4 = idx & 15;
            *(float4*)&Ws[r][c4 * 4] =
                *(const float4*)&W[(size_t)(k0 + r) * HH + c4 * 4];
        }
        __syncthreads();

        #pragma unroll
        for (int kk = 0; kk < 32; kk++) {
            float a[8];
            #pragma unroll
            for (int i = 0; i < 8; i++) a[i] = Xs[tr + 16 * i][kk];  // broadcast
            ull a2[4];
            #pragma unroll
            for (int p = 0; p < 4; p++) a2[p] = pk2(a[2 * p], a[2 * p + 1]);
            float4 bv4 = *(float4*)&Ws[kk][tc * 4];
            ull bd[4] = {pk2(bv4.x, bv4.x), pk2(bv4.y, bv4.y),
                         pk2(bv4.z, bv4.z), pk2(bv4.w, bv4.w)};
            #pragma unroll
            for (int p = 0; p < 4; p++)
                #pragma unroll
                for (int c = 0; c < 4; c++)
                    fma2(acc[p][c], a2[p], bd[c]);
        }
        __syncthreads();
    }

    // epilogue: atomic accumulate (split-K); ks==0 adds bias exactly once.
    float b4[4] = {0.f, 0.f, 0.f, 0.f};
    if (ks == 0) {
        float4 bb = *(const float4*)&bias[tc * 4];
        b4[0] = bb.x; b4[1] = bb.y; b4[2] = bb.z; b4[3] = bb.w;
    }
    #pragma unroll
    for (int p = 0; p < 4; p++) {
        int rlo = m0 + tr + 32 * p;
        int rhi = rlo + 16;
        #pragma unroll
        for (int c = 0; c < 4; c++) {
            float lo, hi; upk2(acc[p][c], lo, hi);
            atomicAdd(&out[(size_t)rlo * HH + tc * 4 + c], lo + b4[c]);
            atomicAdd(&out[(size_t)rhi * HH + tc * 4 + c], hi + b4[c]);
        }
    }
}

// ---------------------------------------------------------------------------
// K2: scores[b][j][i] = q[b,j]·k[b,i], masked (keep i>=j and s!=0), scaled.
// Tile 128(j) x 128(i), grid (16,16,B), 256 threads, two d-passes of 32.
// Per thread 8x8 via FFMA2 (pairs along rows). a broadcast; c conflict-free
// (pad-33 K tile, col = tc + 16j).
// ---------------------------------------------------------------------------
__global__ __launch_bounds__(256, 2)
void scores_kernel() {
    const int it = blockIdx.x, jt = blockIdx.y, b = blockIdx.z;
    if (it < jt) return;  // tile entirely i<j -> softmax synthesizes -inf

    __shared__ __align__(16) float Qs[128][32];
    __shared__ float Ks[128][33];

    const int i0 = it * 128, j0 = jt * 128;
    const int tid = threadIdx.x;
    const int tr = tid >> 4, tc = tid & 15;
    const float* qb = g_q + (size_t)b * NN * HH;
    const float* kb = g_k + (size_t)b * NN * HH;

    ull acc[4][8] = {};  // [row-pair][col j]; pair p = rows (tr+32p, tr+32p+16)

    #pragma unroll
    for (int pass = 0; pass < 2; pass++) {
        const int d0 = pass * 32;
        #pragma unroll
        for (int l = 0; l < 4; l++) {
            int idx = tid + l * 256;
            int r = idx >> 3, c4 = idx & 7;
            *(float4*)&Qs[r][c4 * 4] =
                *(const float4*)&qb[(size_t)(j0 + r) * HH + d0 + c4 * 4];
            float4 v = *(const float4*)&kb[(size_t)(i0 + r) * HH + d0 + c4 * 4];
            Ks[r][c4 * 4 + 0] = v.x; Ks[r][c4 * 4 + 1] = v.y;
            Ks[r][c4 * 4 + 2] = v.z; Ks[r][c4 * 4 + 3] = v.w;
        }
        __syncthreads();

        #pragma unroll
        for (int kk = 0; kk < 32; kk++) {
            float a[8];
            #pragma unroll
            for (int i = 0; i < 8; i++) a[i] = Qs[tr + 16 * i][kk];  // broadcast
            ull a2[4];
            #pragma unroll
            for (int p = 0; p < 4; p++) a2[p] = pk2(a[2 * p], a[2 * p + 1]);
            float c[8];
            #pragma unroll
            for (int j = 0; j < 8; j++) c[j] = Ks[tc + 16 * j][kk];  // conflict-free
            ull cd[8];
            #pragma unroll
            for (int j = 0; j < 8; j++) cd[j] = pk2(c[j], c[j]);
            #pragma unroll
            for (int p = 0; p < 4; p++)
                #pragma unroll
                for (int j = 0; j < 8; j++)
                    fma2(acc[p][j], a2[p], cd[j]);
        }
        __syncthreads();
    }

    float* sb = g_s + (size_t)b * NN * NN;
    #pragma unroll
    for (int p = 0; p < 4; p++) {
        int jlo = j0 + tr + 32 * p;
        int jhi = jlo + 16;
        #pragma unroll
        for (int j = 0; j < 8; j++) {
            int ii = i0 + tc + 16 * j;
            float lo, hi; upk2(acc[p][j], lo, hi);
            // faithful: triu keeps col>=row, exact zeros -> -inf, then *scale.
            sb[(size_t)jlo * NN + ii] =
                (ii >= jlo && lo != 0.0f) ? lo * SCALE : -CUDART_INF_F;
            sb[(size_t)jhi * NN + ii] =
                (ii >= jhi && hi != 0.0f) ? hi * SCALE : -CUDART_INF_F;
        }
    }
}

// ---------------------------------------------------------------------------
// K3: row softmax over i (axis=-1). One 256-thread block per (b,j) row.
// i<j synthesized as -inf without reading; writes attn=0 there.
// ---------------------------------------------------------------------------
__global__ void softmax_kernel() {
    const int row = blockIdx.x;
    const int b = row >> 11;
    const int j = row & (NN - 1);
    float* srow = g_s + (size_t)b * NN * NN + (size_t)j * NN;

    const int tid = threadIdx.x;
    float vals[8];
    float m = -CUDART_INF_F;

    #pragma unroll
    for (int l = 0; l < 8; l++) {
        int ii = tid + l * 256;
        float v = (ii >= j) ? srow[ii] : -CUDART_INF_F;
        vals[l] = v;
        m = fmaxf(m, v);
    }

    __shared__ float red[8];
    #pragma unroll
    for (int o = 16; o > 0; o >>= 1) m = fmaxf(m, __shfl_xor_sync(0xffffffffu, m, o));
    if ((tid & 31) == 0) red[tid >> 5] = m;
    __syncthreads();
    float mt = red[0];
    #pragma unroll
    for (int w = 1; w < 8; w++) mt = fmaxf(mt, red[w]);

    float sum = 0.0f;
    #pragma unroll
    for (int l = 0; l < 8; l++) {
        float e = __expf(vals[l] - mt);
        vals[l] = e;
        sum += e;
    }
    #pragma unroll
    for (int o = 16; o > 0; o >>= 1) sum += __shfl_xor_sync(0xffffffffu, sum, o);
    __syncthreads();
    if ((tid & 31) == 0) red[tid >> 5] = sum;
    __syncthreads();
    float st = 0.0f;
    #pragma unroll
    for (int w = 0; w < 8; w++) st += red[w];

    float inv = 1.0f / st;
    #pragma unroll
    for (int l = 0; l < 8; l++) srow[tid + l * 256] = vals[l] * inv;
}

// ---------------------------------------------------------------------------
// K4: out[b,i,h] = sum_j attn[b,j,i] * v[b,j,h]  (transposed application).
// Split-K over j: i-tiles of 128, j-chunks of 256, atomicAdd into out.
// grid (72, B): 72 = sum over 16 i-tiles of ceil((it+1)/2) chunks.
// Per thread 8(i) x 4(h), FFMA2 pairs along h (pack-free from float4 V).
// ---------------------------------------------------------------------------
__global__ __launch_bounds__(256, 2)
void out_kernel(float* __restrict__ out) {
    int c = blockIdx.x, it = 0;
    for (;;) { int f = (it >> 1) + 1; if (c < f) break; c -= f; it++; }
    const int b = blockIdx.y;
    const int i0 = it * 128;
    const int jbeg = c * 256;
    const int jend = min(jbeg + 256, (it + 1) * 128);

    __shared__ __align__(16) float As[64][128];  // [j][i]
    __shared__ __align__(16) float Vs[64][64];   // [j][h]

    const int tid = threadIdx.x;
    const int tr = tid >> 4, tc = tid & 15;

    ull acc[8][2] = {};  // [i-row][h-pair]

    const float* ab = g_s + (size_t)b * NN * NN;
    const float* vb = g_v + (size_t)b * NN * HH;

    for (int j0 = jbeg; j0 < jend; j0 += 64) {
        #pragma unroll
        for (int l = 0; l < 8; l++) {
            int idx = tid + l * 256;      // 2048 float4 slots (64x128)
            int r = idx >> 5, c4 = idx & 31;
            *(float4*)&As[r][c4 * 4] =
                *(const float4*)&ab[(size_t)(j0 + r) * NN + i0 + c4 * 4];
        }
        #pragma unroll
        for (int l = 0; l < 4; l++) {
            int idx = tid + l * 256;      // 1024 float4 slots (64x64)
            int r = idx >> 4, c4 = idx & 15;
            *(float4*)&Vs[r][c4 * 4] =
                *(const float4*)&vb[(size_t)(j0 + r) * HH + c4 * 4];
        }
        __syncthreads();

        #pragma unroll
        for (int jj = 0; jj < 64; jj++) {
            float4 vv = *(float4*)&Vs[jj][tc * 4];
            ull v0 = pk2(vv.x, vv.y), v1 = pk2(vv.z, vv.w);
            #pragma unroll
            for (int i = 0; i < 8; i++) {
                float a = As[jj][tr + 16 * i];  // broadcast
                ull ad = pk2(a, a);
                fma2(acc[i][0], ad, v0);
                fma2(acc[i][1], ad, v1);
            }
            // (ptxas will interleave; FFMA2 pipe-bound)
        }
        __syncthreads();
    }

    #pragma unroll
    for (int i = 0; i < 8; i++) {
        int r = i0 + tr + 16 * i;
        float* op = &out[(size_t)b * NN * HH + (size_t)r * HH + tc * 4];
        float lo, hi;
        upk2(acc[i][0], lo, hi);
        atomicAdd(op + 0, lo); atomicAdd(op + 1, hi);
        upk2(acc[i][1], lo, hi);
        atomicAdd(op + 2, lo); atomicAdd(op + 3, hi);
    }
}

// ---------------------------------------------------------------------------
extern "C" void kernel_launch(void* const* d_in, const int* in_sizes, int n_in,
                              void* d_out, int out_size) {
    const float* x  = (const float*)d_in[0];
    const float* Wq = (const float*)d_in[1];
    const float* bq = (const float*)d_in[2];
    const float* Wk = (const float*)d_in[3];
    const float* bk = (const float*)d_in[4];
    const float* Wv = (const float*)d_in[5];
    const float* bv = (const float*)d_in[6];
    float* out = (float*)d_out;

    zero_kernel<<<512, 256>>>(out);

    dim3 g1((BB * NN) / 128, 2, 3);   // 64 m-tiles, split-K 2, 3 projections
    qkv_kernel<<<g1, 256>>>(x, Wq, bq, Wk, bk, Wv, bv);

    dim3 g2(NN / 128, NN / 128, BB);  // (16,16,4)
    scores_kernel<<<g2, 256>>>();

    softmax_kernel<<<BB * NN, 256>>>();

    dim3 g4(72, BB);
    out_kernel<<<g4, 256>>>(out);
}

// round 6
// speedup vs baseline: 1.4922x; 1.0333x over previous
#include <cuda_runtime.h>
#include <cuda_bf16.h>
#include <math_constants.h>
#include <cstdint>

#define BB 4
#define NN 2048
#define DD 1024
#define HH 64
#define SCALE 0.125f /* H^-0.5 */

// Scratch (allocation-free rule: __device__ globals)
__device__ float g_q[BB * NN * HH];
__device__ float g_k[BB * NN * HH];
__device__ float g_v[BB * NN * HH];
__device__ float g_s[(size_t)BB * NN * NN];  // scores, then attn (in place)

// ======================= helpers ==========================================
__device__ __forceinline__ uint32_t smem_u32(const void* p) {
    uint32_t a;
    asm("{ .reg .u64 t; cvta.to.shared.u64 t, %1; cvt.u32.u64 %0, t; }"
        : "=r"(a) : "l"(p));
    return a;
}

__device__ __forceinline__ void ldsm4(uint32_t r[4], uint32_t a) {
    asm volatile("ldmatrix.sync.aligned.m8n8.x4.shared.b16 {%0,%1,%2,%3}, [%4];"
                 : "=r"(r[0]), "=r"(r[1]), "=r"(r[2]), "=r"(r[3]) : "r"(a));
}
__device__ __forceinline__ void ldsm4t(uint32_t r[4], uint32_t a) {
    asm volatile("ldmatrix.sync.aligned.m8n8.x4.trans.shared.b16 {%0,%1,%2,%3}, [%4];"
                 : "=r"(r[0]), "=r"(r[1]), "=r"(r[2]), "=r"(r[3]) : "r"(a));
}
__device__ __forceinline__ void ldsm2(uint32_t r[2], uint32_t a) {
    asm volatile("ldmatrix.sync.aligned.m8n8.x2.shared.b16 {%0,%1}, [%2];"
                 : "=r"(r[0]), "=r"(r[1]) : "r"(a));
}
__device__ __forceinline__ void ldsm2t(uint32_t r[2], uint32_t a) {
    asm volatile("ldmatrix.sync.aligned.m8n8.x2.trans.shared.b16 {%0,%1}, [%2];"
                 : "=r"(r[0]), "=r"(r[1]) : "r"(a));
}

__device__ __forceinline__ void mma_bf16(float c[4], const uint32_t a[4],
                                         const uint32_t b[2]) {
    asm volatile(
        "mma.sync.aligned.m16n8k16.row.col.f32.bf16.bf16.f32 "
        "{%0,%1,%2,%3}, {%4,%5,%6,%7}, {%8,%9}, {%0,%1,%2,%3};"
        : "+f"(c[0]), "+f"(c[1]), "+f"(c[2]), "+f"(c[3])
        : "r"(a[0]), "r"(a[1]), "r"(a[2]), "r"(a[3]), "r"(b[0]), "r"(b[1]));
}

// pack two floats -> bf16x2 (e0 low half, e1 high half)
__device__ __forceinline__ uint32_t bf2(float e0, float e1) {
    uint32_t r;
    asm("cvt.rn.bf16x2.f32 %0, %1, %2;" : "=r"(r) : "f"(e1), "f"(e0));
    return r;
}
__device__ __forceinline__ float bhi(float x) {
    return __bfloat162float(__float2bfloat16_rn(x));
}
// split a float4 into bf16 hi/lo pairs and store 8 bytes at each dst
__device__ __forceinline__ void split_store4(char* hdst, char* ldst, float4 v) {
    float hx = bhi(v.x), hy = bhi(v.y), hz = bhi(v.z), hw = bhi(v.w);
    uint2 ph, pl;
    ph.x = bf2(hx, hy); ph.y = bf2(hz, hw);
    pl.x = bf2(v.x - hx, v.y - hy);
    pl.y = bf2(v.z - hz, v.w - hw);
    *(uint2*)hdst = ph;
    *(uint2*)ldst = pl;
}

// ---------------------------------------------------------------------------
// K0: zero out (accumulated via atomics in out_kernel).
// ---------------------------------------------------------------------------
__global__ void zero_kernel(float* __restrict__ out) {
    int idx = blockIdx.x * 256 + threadIdx.x;  // 131072 float4 = BB*NN*HH
    *(float4*)&out[idx * 4] = make_float4(0.f, 0.f, 0.f, 0.f);
}

// ---------------------------------------------------------------------------
// K1: q/k/v = x @ W + b via mma.sync bf16 (hi/lo split, 3 products).
// grid (64, 3), 256 threads = 8 warps; tile M=128, N=64, K-chunks of 64.
// SMEM rows padded to 144B (72 bf16) -> conflict-free ldmatrix.
// ---------------------------------------------------------------------------
#define QKV_XH 0                 /* 128 x 144B = 18432 */
#define QKV_XL 18432
#define QKV_WH 36864             /* 64 x 144B = 9216 */
#define QKV_WL 46080
#define QKV_SMEM 55296

__global__ __launch_bounds__(256, 2)
void qkv_kernel(const float* __restrict__ x,
                const float* __restrict__ Wq, const float* __restrict__ bq,
                const float* __restrict__ Wk, const float* __restrict__ bk,
                const float* __restrict__ Wv, const float* __restrict__ bv) {
    extern __shared__ char sm[];
    const int proj = blockIdx.y;
    const float* W    = proj == 0 ? Wq : (proj == 1 ? Wk : Wv);
    const float* bias = proj == 0 ? bq : (proj == 1 ? bk : bv);
    float* out        = proj == 0 ? g_q : (proj == 1 ? g_k : g_v);

    const uint32_t sb = smem_u32(sm);
    const int tid = threadIdx.x;
    const int wid = tid >> 5, lane = tid & 31;
    const int m0 = blockIdx.x * 128;

    // ldmatrix per-lane address components
    const int arow   = lane & 15;
    const int akhalf = (lane >> 4) * 8;         // A: k halves across lane quads
    const int brow   = lane & 7;
    const int bkhalf = ((lane >> 3) & 1) * 8;   // B: lanes 0-15 used

    float C[8][4] = {};

    for (int ch = 0; ch < 16; ch++) {
        const int k0 = ch * 64;
        // X tile 128x64 -> hi/lo bf16
        #pragma unroll
        for (int l = 0; l < 8; l++) {
            int idx = tid + l * 256;        // 2048 float4 (128 rows x 16)
            int r = idx >> 4, c4 = idx & 15;
            float4 v = *(const float4*)&x[(size_t)(m0 + r) * DD + k0 + c4 * 4];
            int off = r * 144 + c4 * 8;
            split_store4(sm + QKV_XH + off, sm + QKV_XL + off, v);
        }
        // W tile 64k x 64n -> transposed Ws[n][k], hi/lo
        #pragma unroll
        for (int l = 0; l < 4; l++) {
            int idx = tid + l * 256;        // 1024 float4 (64 k-rows x 16)
            int kk = idx >> 4, n4 = idx & 15;
            float4 v = *(const float4*)&W[(size_t)(k0 + kk) * HH + n4 * 4];
            float vv[4] = {v.x, v.y, v.z, v.w};
            #pragma unroll
            for (int j = 0; j < 4; j++) {
                int n = n4 * 4 + j;
                float h = bhi(vv[j]);
                *(__nv_bfloat16*)(sm + QKV_WH + n * 144 + kk * 2) =
                    __float2bfloat16_rn(h);
                *(__nv_bfloat16*)(sm + QKV_WL + n * 144 + kk * 2) =
                    __float2bfloat16_rn(vv[j] - h);
            }
        }
        __syncthreads();

        #pragma unroll
        for (int ks = 0; ks < 4; ks++) {
            uint32_t aaddr = sb + QKV_XH + (wid * 16 + arow) * 144 +
                             (ks * 16 + akhalf) * 2;
            uint32_t ah[4], al[4];
            ldsm4(ah, aaddr);
            ldsm4(al, aaddr + (QKV_XL - QKV_XH));
            #pragma unroll
            for (int nc = 0; nc < 8; nc++) {
                uint32_t baddr = sb + QKV_WH + (nc * 8 + brow) * 144 +
                                 (ks * 16 + bkhalf) * 2;
                uint32_t bh[2], bl[2];
                ldsm2(bh, baddr);
                ldsm2(bl, baddr + (QKV_WL - QKV_WH));
                mma_bf16(C[nc], ah, bh);
                mma_bf16(C[nc], ah, bl);
                mma_bf16(C[nc], al, bh);
            }
        }
        __syncthreads();
    }

    const int grp = lane >> 2, q4 = lane & 3;
    const int r0 = m0 + wid * 16 + grp;
    #pragma unroll
    for (int nc = 0; nc < 8; nc++) {
        int col = nc * 8 + q4 * 2;
        float b0 = __ldg(&bias[col]), b1 = __ldg(&bias[col + 1]);
        float2 o0 = {C[nc][0] + b0, C[nc][1] + b1};
        float2 o1 = {C[nc][2] + b0, C[nc][3] + b1};
        *(float2*)&out[(size_t)r0 * HH + col] = o0;
        *(float2*)&out[(size_t)(r0 + 8) * HH + col] = o1;
    }
}

// ---------------------------------------------------------------------------
// K2: scores[b][j][i] = q[b,j]·k[b,i], masked (keep i>=j and s!=0), scaled.
// Tile 128(j) x 64(i), grid (32,16,B), cull if it < 2*jt.
// 8 warps = 4(j) x 2(i); per warp 32j x 32i (2 m16 strips x 4 n8 chunks).
// ---------------------------------------------------------------------------
#define SC_QH 0                  /* 128 x 144B */
#define SC_QL 18432
#define SC_KH 36864              /* 64 x 144B */
#define SC_KL 46080
#define SC_SMEM 55296

__global__ __launch_bounds__(256, 2)
void scores_kernel() {
    const int it = blockIdx.x, jt = blockIdx.y, b = blockIdx.z;
    if (it < 2 * jt) return;  // whole tile i<j -> softmax synthesizes -inf

    extern __shared__ char sm[];
    const uint32_t sb = smem_u32(sm);
    const int i0 = it * 64, j0 = jt * 128;
    const int tid = threadIdx.x;
    const int wid = tid >> 5, lane = tid & 31;
    const int wj = wid >> 1, wi = wid & 1;    // 4 x 2 warp grid
    const int j0w = wj * 32, i0w = wi * 32;

    const float* qb = g_q + (size_t)b * NN * HH;
    const float* kb = g_k + (size_t)b * NN * HH;

    // Q tile 128x64 fp32 -> hi/lo
    #pragma unroll
    for (int l = 0; l < 8; l++) {
        int idx = tid + l * 256;
        int r = idx >> 4, c4 = idx & 15;
        float4 v = *(const float4*)&qb[(size_t)(j0 + r) * HH + c4 * 4];
        int off = r * 144 + c4 * 8;
        split_store4(sm + SC_QH + off, sm + SC_QL + off, v);
    }
    // K tile 64x64 fp32 -> hi/lo
    #pragma unroll
    for (int l = 0; l < 4; l++) {
        int idx = tid + l * 256;
        int r = idx >> 4, c4 = idx & 15;
        float4 v = *(const float4*)&kb[(size_t)(i0 + r) * HH + c4 * 4];
        int off = r * 144 + c4 * 8;
        split_store4(sm + SC_KH + off, sm + SC_KL + off, v);
    }
    __syncthreads();

    const int arow   = lane & 15;
    const int akhalf = (lane >> 4) * 8;
    const int brow   = lane & 7;
    const int bkhalf = ((lane >> 3) & 1) * 8;

    float C[2][4][4] = {};

    #pragma unroll
    for (int ks = 0; ks < 4; ks++) {
        uint32_t ah[2][4], al[2][4];
        #pragma unroll
        for (int s = 0; s < 2; s++) {
            uint32_t aaddr = sb + SC_QH + (j0w + s * 16 + arow) * 144 +
                             (ks * 16 + akhalf) * 2;
            ldsm4(ah[s], aaddr);
            ldsm4(al[s], aaddr + (SC_QL - SC_QH));
        }
        #pragma unroll
        for (int nc = 0; nc < 4; nc++) {
            uint32_t baddr = sb + SC_KH + (i0w + nc * 8 + brow) * 144 +
                             (ks * 16 + bkhalf) * 2;
            uint32_t bh[2], bl[2];
            ldsm2(bh, baddr);
            ldsm2(bl, baddr + (SC_KL - SC_KH));
            #pragma unroll
            for (int s = 0; s < 2; s++) {
                mma_bf16(C[s][nc], ah[s], bh);
                mma_bf16(C[s][nc], ah[s], bl);
                mma_bf16(C[s][nc], al[s], bh);
            }
        }
    }

    float* sbm = g_s + (size_t)b * NN * NN;
    const int grp = lane >> 2, q4 = lane & 3;
    #pragma unroll
    for (int s = 0; s < 2; s++) {
        int jlo = j0 + j0w + s * 16 + grp;
        int jhi = jlo + 8;
        #pragma unroll
        for (int nc = 0; nc < 4; nc++) {
            int ii = i0 + i0w + nc * 8 + q4 * 2;
            float v00 = C[s][nc][0], v01 = C[s][nc][1];
            float v10 = C[s][nc][2], v11 = C[s][nc][3];
            float2 o0, o1;
            o0.x = (ii     >= jlo && v00 != 0.0f) ? v00 * SCALE : -CUDART_INF_F;
            o0.y = (ii + 1 >= jlo && v01 != 0.0f) ? v01 * SCALE : -CUDART_INF_F;
            o1.x = (ii     >= jhi && v10 != 0.0f) ? v10 * SCALE : -CUDART_INF_F;
            o1.y = (ii + 1 >= jhi && v11 != 0.0f) ? v11 * SCALE : -CUDART_INF_F;
            *(float2*)&sbm[(size_t)jlo * NN + ii] = o0;
            *(float2*)&sbm[(size_t)jhi * NN + ii] = o1;
        }
    }
}

// ---------------------------------------------------------------------------
// K3: row softmax over i (axis=-1). One 256-thread block per (b,j) row.
// ---------------------------------------------------------------------------
__global__ void softmax_kernel() {
    const int row = blockIdx.x;
    const int b = row >> 11;
    const int j = row & (NN - 1);
    float* srow = g_s + (size_t)b * NN * NN + (size_t)j * NN;

    const int tid = threadIdx.x;
    float vals[8];
    float m = -CUDART_INF_F;

    #pragma unroll
    for (int l = 0; l < 8; l++) {
        int ii = tid + l * 256;
        float v = (ii >= j) ? srow[ii] : -CUDART_INF_F;
        vals[l] = v;
        m = fmaxf(m, v);
    }

    __shared__ float red[8];
    #pragma unroll
    for (int o = 16; o > 0; o >>= 1) m = fmaxf(m, __shfl_xor_sync(0xffffffffu, m, o));
    if ((tid & 31) == 0) red[tid >> 5] = m;
    __syncthreads();
    float mt = red[0];
    #pragma unroll
    for (int w = 1; w < 8; w++) mt = fmaxf(mt, red[w]);

    float sum = 0.0f;
    #pragma unroll
    for (int l = 0; l < 8; l++) {
        float e = __expf(vals[l] - mt);
        vals[l] = e;
        sum += e;
    }
    #pragma unroll
    for (int o = 16; o > 0; o >>= 1) sum += __shfl_xor_sync(0xffffffffu, sum, o);
    __syncthreads();
    if ((tid & 31) == 0) red[tid >> 5] = sum;
    __syncthreads();
    float st = 0.0f;
    #pragma unroll
    for (int w = 0; w < 8; w++) st += red[w];

    float inv = 1.0f / st;
    #pragma unroll
    for (int l = 0; l < 8; l++) srow[tid + l * 256] = vals[l] * inv;
}

// ---------------------------------------------------------------------------
// K4: out[b,i,h] = sum_j attn[b,j,i] * v[b,j,h]  (transposed application).
// Split-K over j: i-tiles of 128, j-chunks of 256, atomicAdd into out.
// grid (72, B). 8 warps = 4(i) x 2(h); per warp 32i x 32h.
// attn fragments via ldmatrix.trans on [j][i]; v via ldmatrix.trans on [j][h].
// ---------------------------------------------------------------------------
#define OT_AH 0                  /* 64 x 272B = 17408 */
#define OT_AL 17408
#define OT_VH 34816              /* 64 x 144B = 9216 */
#define OT_VL 44032
#define OT_SMEM 53248

__global__ __launch_bounds__(256, 2)
void out_kernel(float* __restrict__ out) {
    int c = blockIdx.x, it = 0;
    for (;;) { int f = (it >> 1) + 1; if (c < f) break; c -= f; it++; }
    const int b = blockIdx.y;
    const int i0 = it * 128;
    const int jbeg = c * 256;
    const int jend = min(jbeg + 256, (it + 1) * 128);

    extern __shared__ char sm[];
    const uint32_t sb = smem_u32(sm);
    const int tid = threadIdx.x;
    const int wid = tid >> 5, lane = tid & 31;
    const int wi = wid >> 1, wh = wid & 1;     // 4 x 2 warp grid
    const int i0w = wi * 32, h0w = wh * 32;

    const float* ab = g_s + (size_t)b * NN * NN;
    const float* vb = g_v + (size_t)b * NN * HH;

    // trans-ldmatrix per-lane row/col components
    const int atr = ((lane >> 4) & 1) * 8 + (lane & 7);  // j row offset (A)
    const int atc = ((lane >> 3) & 1) * 8;               // i col half (A)
    const int btr = ((lane >> 3) & 1) * 8 + (lane & 7);  // j row offset (B)

    float C[2][4][4] = {};

    for (int j0 = jbeg; j0 < jend; j0 += 64) {
        // attn 64x128 fp32 -> hi/lo
        #pragma unroll
        for (int l = 0; l < 8; l++) {
            int idx = tid + l * 256;          // 2048 float4 (64 x 32)
            int r = idx >> 5, c4 = idx & 31;
            float4 v = *(const float4*)&ab[(size_t)(j0 + r) * NN + i0 + c4 * 4];
            int off = r * 272 + c4 * 8;
            split_store4(sm + OT_AH + off, sm + OT_AL + off, v);
        }
        // v 64x64 fp32 -> hi/lo
        #pragma unroll
        for (int l = 0; l < 4; l++) {
            int idx = tid + l * 256;          // 1024 float4 (64 x 16)
            int r = idx >> 4, c4 = idx & 15;
            float4 v = *(const float4*)&vb[(size_t)(j0 + r) * HH + c4 * 4];
            int off = r * 144 + c4 * 8;
            split_store4(sm + OT_VH + off, sm + OT_VL + off, v);
        }
        __syncthreads();

        #pragma unroll
        for (int ks = 0; ks < 4; ks++) {
            uint32_t ah[2][4], al[2][4];
            #pragma unroll
            for (int s = 0; s < 2; s++) {
                uint32_t aaddr = sb + OT_AH + (ks * 16 + atr) * 272 +
                                 (i0w + s * 16 + atc) * 2;
                ldsm4t(ah[s], aaddr);
                ldsm4t(al[s], aaddr + (OT_AL - OT_AH));
            }
            #pragma unroll
            for (int nc = 0; nc < 4; nc++) {
                uint32_t baddr = sb + OT_VH + (ks * 16 + btr) * 144 +
                                 (h0w + nc * 8) * 2;
                uint32_t bh[2], bl[2];
                ldsm2t(bh, baddr);
                ldsm2t(bl, baddr + (OT_VL - OT_VH));
                #pragma unroll
                for (int s = 0; s < 2; s++) {
                    mma_bf16(C[s][nc], ah[s], bh);
                    mma_bf16(C[s][nc], ah[s], bl);
                    mma_bf16(C[s][nc], al[s], bh);
                }
            }
        }
        __syncthreads();
    }

    const int grp = lane >> 2, q4 = lane & 3;
    #pragma unroll
    for (int s = 0; s < 2; s++) {
        int rlo = i0 + i0w + s * 16 + grp;
        int rhi = rlo + 8;
        #pragma unroll
        for (int nc = 0; nc < 4; nc++) {
            int hcol = h0w + nc * 8 + q4 * 2;
            float* p0 = &out[(size_t)b * NN * HH + (size_t)rlo * HH + hcol];
            float* p1 = &out[(size_t)b * NN * HH + (size_t)rhi * HH + hcol];
            atomicAdd(p0,     C[s][nc][0]);
            atomicAdd(p0 + 1, C[s][nc][1]);
            atomicAdd(p1,     C[s][nc][2]);
            atomicAdd(p1 + 1, C[s][nc][3]);
        }
    }
}

// ---------------------------------------------------------------------------
extern "C" void kernel_launch(void* const* d_in, const int* in_sizes, int n_in,
                              void* d_out, int out_size) {
    const float* x  = (const float*)d_in[0];
    const float* Wq = (const float*)d_in[1];
    const float* bq = (const float*)d_in[2];
    const float* Wk = (const float*)d_in[3];
    const float* bk = (const float*)d_in[4];
    const float* Wv = (const float*)d_in[5];
    const float* bv = (const float*)d_in[6];
    float* out = (float*)d_out;

    cudaFuncSetAttribute(qkv_kernel,
                         cudaFuncAttributeMaxDynamicSharedMemorySize, QKV_SMEM);
    cudaFuncSetAttribute(scores_kernel,
                         cudaFuncAttributeMaxDynamicSharedMemorySize, SC_SMEM);
    cudaFuncSetAttribute(out_kernel,
                         cudaFuncAttributeMaxDynamicSharedMemorySize, OT_SMEM);

    zero_kernel<<<512, 256>>>(out);

    dim3 g1((BB * NN) / 128, 3);
    qkv_kernel<<<g1, 256, QKV_SMEM>>>(x, Wq, bq, Wk, bk, Wv, bv);

    dim3 g2(NN / 64, NN / 128, BB);   // (32,16,4), culled by it<2*jt
    scores_kernel<<<g2, 256, SC_SMEM>>>();

    softmax_kernel<<<BB * NN, 256>>>();

    dim3 g4(72, BB);
    out_kernel<<<g4, 256, OT_SMEM>>>(out);
}

// round 7
// speedup vs baseline: 2.5248x; 1.6920x over previous
#include <cuda_runtime.h>
#include <cuda_bf16.h>
#include <math_constants.h>
#include <cstdint>

#define BB 4
#define NN 2048
#define DD 1024
#define HH 64
#define SCALE 0.125f /* H^-0.5 */

// Scratch (allocation-free rule: __device__ globals)
__device__ __align__(16) __nv_bfloat16 g_xh[BB * NN * DD];
__device__ __align__(16) __nv_bfloat16 g_xl[BB * NN * DD];
__device__ __align__(16) __nv_bfloat16 g_wth[3 * HH * DD];  // [proj][n][k]
__device__ __align__(16) __nv_bfloat16 g_wtl[3 * HH * DD];
__device__ __align__(16) __nv_bfloat16 g_qh[BB * NN * HH];
__device__ __align__(16) __nv_bfloat16 g_ql[BB * NN * HH];
__device__ __align__(16) __nv_bfloat16 g_kh[BB * NN * HH];
__device__ __align__(16) __nv_bfloat16 g_kl[BB * NN * HH];
__device__ __align__(16) __nv_bfloat16 g_vh[BB * NN * HH];
__device__ __align__(16) __nv_bfloat16 g_vl[BB * NN * HH];
__device__ float g_s[(size_t)BB * NN * NN];                 // raw masked scores
__device__ __align__(16) __nv_bfloat16 g_ah[(size_t)BB * NN * NN];  // attn hi
__device__ __align__(16) __nv_bfloat16 g_al[(size_t)BB * NN * NN];  // attn lo

// ======================= helpers ==========================================
__device__ __forceinline__ uint32_t smem_u32(const void* p) {
    uint32_t a;
    asm("{ .reg .u64 t; cvta.to.shared.u64 t, %1; cvt.u32.u64 %0, t; }"
        : "=r"(a) : "l"(p));
    return a;
}

__device__ __forceinline__ void ldsm4(uint32_t r[4], uint32_t a) {
    asm volatile("ldmatrix.sync.aligned.m8n8.x4.shared.b16 {%0,%1,%2,%3}, [%4];"
                 : "=r"(r[0]), "=r"(r[1]), "=r"(r[2]), "=r"(r[3]) : "r"(a));
}
__device__ __forceinline__ void ldsm4t(uint32_t r[4], uint32_t a) {
    asm volatile("ldmatrix.sync.aligned.m8n8.x4.trans.shared.b16 {%0,%1,%2,%3}, [%4];"
                 : "=r"(r[0]), "=r"(r[1]), "=r"(r[2]), "=r"(r[3]) : "r"(a));
}
__device__ __forceinline__ void ldsm2(uint32_t r[2], uint32_t a) {
    asm volatile("ldmatrix.sync.aligned.m8n8.x2.shared.b16 {%0,%1}, [%2];"
                 : "=r"(r[0]), "=r"(r[1]) : "r"(a));
}
__device__ __forceinline__ void ldsm2t(uint32_t r[2], uint32_t a) {
    asm volatile("ldmatrix.sync.aligned.m8n8.x2.trans.shared.b16 {%0,%1}, [%2];"
                 : "=r"(r[0]), "=r"(r[1]) : "r"(a));
}

__device__ __forceinline__ void mma_bf16(float c[4], const uint32_t a[4],
                                         const uint32_t b[2]) {
    asm volatile(
        "mma.sync.aligned.m16n8k16.row.col.f32.bf16.bf16.f32 "
        "{%0,%1,%2,%3}, {%4,%5,%6,%7}, {%8,%9}, {%0,%1,%2,%3};"
        : "+f"(c[0]), "+f"(c[1]), "+f"(c[2]), "+f"(c[3])
        : "r"(a[0]), "r"(a[1]), "r"(a[2]), "r"(a[3]), "r"(b[0]), "r"(b[1]));
}

// pack two floats -> bf16x2 (e0 low half, e1 high half)
__device__ __forceinline__ uint32_t bf2(float e0, float e1) {
    uint32_t r;
    asm("cvt.rn.bf16x2.f32 %0, %1, %2;" : "=r"(r) : "f"(e1), "f"(e0));
    return r;
}
__device__ __forceinline__ float bhi(float x) {
    return __bfloat162float(__float2bfloat16_rn(x));
}
// split a float4 into bf16 hi/lo pairs, store 8 bytes at each dst
__device__ __forceinline__ void split_store4(char* hdst, char* ldst, float4 v) {
    float hx = bhi(v.x), hy = bhi(v.y), hz = bhi(v.z), hw = bhi(v.w);
    uint2 ph, pl;
    ph.x = bf2(hx, hy); ph.y = bf2(hz, hw);
    pl.x = bf2(v.x - hx, v.y - hy);
    pl.y = bf2(v.z - hz, v.w - hw);
    *(uint2*)hdst = ph;
    *(uint2*)ldst = pl;
}

// ---------------------------------------------------------------------------
// K0: prep — zero out, split x -> g_xh/g_xl, split+transpose W -> g_wth/g_wtl
// grid 8192 x 256 (2,097,152 threads == number of float4 in x).
// ---------------------------------------------------------------------------
__global__ void prep_kernel(const float* __restrict__ x,
                            const float* __restrict__ Wq,
                            const float* __restrict__ Wk,
                            const float* __restrict__ Wv,
                            float* __restrict__ out) {
    const int t = blockIdx.x * 256 + threadIdx.x;

    if (t < (BB * NN * HH) / 4)
        *(float4*)&out[t * 4] = make_float4(0.f, 0.f, 0.f, 0.f);

    // x: one float4 per thread
    {
        float4 v = *(const float4*)&x[(size_t)t * 4];
        split_store4((char*)&g_xh[(size_t)t * 4], (char*)&g_xl[(size_t)t * 4], v);
    }

    // W: scalar transpose-split, 3*1024*64 = 196608 elements
    if (t < 3 * DD * HH) {
        int p = t >> 16;            // t / 65536
        int rem = t & 65535;
        int k = rem >> 6, n = rem & 63;
        const float* W = p == 0 ? Wq : (p == 1 ? Wk : Wv);
        float v = W[rem];
        float h = bhi(v);
        int dst = p * (HH * DD) + n * DD + k;
        g_wth[dst] = __float2bfloat16_rn(h);
        g_wtl[dst] = __float2bfloat16_rn(v - h);
    }
}

// ---------------------------------------------------------------------------
// K1: q/k/v = x @ W + b via mma.sync bf16 (hi/lo, 3 products).
// grid (64, 3), 256 threads; tile M=128, N=64, K-chunks of 64.
// Fill = pure uint4 copies of pre-split operands. Epilogue writes bf16 hi/lo.
// ---------------------------------------------------------------------------
#define QKV_XH 0                 /* 128 x 144B = 18432 */
#define QKV_XL 18432
#define QKV_WH 36864             /* 64 x 144B = 9216 */
#define QKV_WL 46080
#define QKV_SMEM 55296

__global__ __launch_bounds__(256, 2)
void qkv_kernel(const float* __restrict__ bq, const float* __restrict__ bk,
                const float* __restrict__ bv) {
    extern __shared__ char sm[];
    const int proj = blockIdx.y;
    const float* bias = proj == 0 ? bq : (proj == 1 ? bk : bv);
    __nv_bfloat16* oh = proj == 0 ? g_qh : (proj == 1 ? g_kh : g_vh);
    __nv_bfloat16* ol = proj == 0 ? g_ql : (proj == 1 ? g_kl : g_vl);
    const __nv_bfloat16* wth = g_wth + proj * (HH * DD);
    const __nv_bfloat16* wtl = g_wtl + proj * (HH * DD);

    const uint32_t sb = smem_u32(sm);
    const int tid = threadIdx.x;
    const int wid = tid >> 5, lane = tid & 31;
    const int m0 = blockIdx.x * 128;

    const int arow   = lane & 15;
    const int akhalf = (lane >> 4) * 8;
    const int brow   = lane & 7;
    const int bkhalf = ((lane >> 3) & 1) * 8;

    float C[8][4] = {};

    for (int ch = 0; ch < 16; ch++) {
        const int k0 = ch * 64;
        // X tile 128x64: 1024 uint4 per array
        #pragma unroll
        for (int l = 0; l < 4; l++) {
            int idx = tid + l * 256;
            int r = idx >> 3, c = idx & 7;
            size_t src = (size_t)(m0 + r) * DD + k0 + c * 8;
            int off = r * 144 + c * 16;
            *(uint4*)(sm + QKV_XH + off) = *(const uint4*)&g_xh[src];
            *(uint4*)(sm + QKV_XL + off) = *(const uint4*)&g_xl[src];
        }
        // W^T tile 64n x 64k: 512 uint4 per array
        #pragma unroll
        for (int l = 0; l < 2; l++) {
            int idx = tid + l * 256;
            int n = idx >> 3, c = idx & 7;
            size_t src = (size_t)n * DD + k0 + c * 8;
            int off = n * 144 + c * 16;
            *(uint4*)(sm + QKV_WH + off) = *(const uint4*)&wth[src];
            *(uint4*)(sm + QKV_WL + off) = *(const uint4*)&wtl[src];
        }
        __syncthreads();

        #pragma unroll
        for (int ks = 0; ks < 4; ks++) {
            uint32_t aaddr = sb + QKV_XH + (wid * 16 + arow) * 144 +
                             (ks * 16 + akhalf) * 2;
            uint32_t ah[4], al[4];
            ldsm4(ah, aaddr);
            ldsm4(al, aaddr + (QKV_XL - QKV_XH));
            #pragma unroll
            for (int nc = 0; nc < 8; nc++) {
                uint32_t baddr = sb + QKV_WH + (nc * 8 + brow) * 144 +
                                 (ks * 16 + bkhalf) * 2;
                uint32_t bh[2], bl[2];
                ldsm2(bh, baddr);
                ldsm2(bl, baddr + (QKV_WL - QKV_WH));
                mma_bf16(C[nc], ah, bh);
                mma_bf16(C[nc], ah, bl);
                mma_bf16(C[nc], al, bh);
            }
        }
        __syncthreads();
    }

    const int grp = lane >> 2, q4 = lane & 3;
    const int r0 = m0 + wid * 16 + grp;
    #pragma unroll
    for (int nc = 0; nc < 8; nc++) {
        int col = nc * 8 + q4 * 2;
        float b0 = __ldg(&bias[col]), b1 = __ldg(&bias[col + 1]);
        float v00 = C[nc][0] + b0, v01 = C[nc][1] + b1;
        float v10 = C[nc][2] + b0, v11 = C[nc][3] + b1;
        float h00 = bhi(v00), h01 = bhi(v01), h10 = bhi(v10), h11 = bhi(v11);
        *(uint32_t*)&oh[(size_t)r0 * HH + col]       = bf2(h00, h01);
        *(uint32_t*)&ol[(size_t)r0 * HH + col]       = bf2(v00 - h00, v01 - h01);
        *(uint32_t*)&oh[(size_t)(r0 + 8) * HH + col] = bf2(h10, h11);
        *(uint32_t*)&ol[(size_t)(r0 + 8) * HH + col] = bf2(v10 - h10, v11 - h11);
    }
}

// ---------------------------------------------------------------------------
// K2: scores[b][j][i] = q[b,j]·k[b,i], masked (keep i>=j and s!=0), scaled.
// Tile 128(j) x 64(i), grid (32,16,B), cull if it < 2*jt. Pure-copy fills.
// ---------------------------------------------------------------------------
#define SC_QH 0                  /* 128 x 144B */
#define SC_QL 18432
#define SC_KH 36864              /* 64 x 144B */
#define SC_KL 46080
#define SC_SMEM 55296

__global__ __launch_bounds__(256, 2)
void scores_kernel() {
    const int it = blockIdx.x, jt = blockIdx.y, b = blockIdx.z;
    if (it < 2 * jt) return;  // whole tile i<j -> softmax synthesizes -inf

    extern __shared__ char sm[];
    const uint32_t sb = smem_u32(sm);
    const int i0 = it * 64, j0 = jt * 128;
    const int tid = threadIdx.x;
    const int wid = tid >> 5, lane = tid & 31;
    const int wj = wid >> 1, wi = wid & 1;
    const int j0w = wj * 32, i0w = wi * 32;

    const size_t boff = (size_t)b * NN * HH;

    // Q strip 128x64: 1024 uint4 per array
    #pragma unroll
    for (int l = 0; l < 4; l++) {
        int idx = tid + l * 256;
        int r = idx >> 3, c = idx & 7;
        size_t src = boff + (size_t)(j0 + r) * HH + c * 8;
        int off = r * 144 + c * 16;
        *(uint4*)(sm + SC_QH + off) = *(const uint4*)&g_qh[src];
        *(uint4*)(sm + SC_QL + off) = *(const uint4*)&g_ql[src];
    }
    // K tile 64x64: 512 uint4 per array
    #pragma unroll
    for (int l = 0; l < 2; l++) {
        int idx = tid + l * 256;
        int r = idx >> 3, c = idx & 7;
        size_t src = boff + (size_t)(i0 + r) * HH + c * 8;
        int off = r * 144 + c * 16;
        *(uint4*)(sm + SC_KH + off) = *(const uint4*)&g_kh[src];
        *(uint4*)(sm + SC_KL + off) = *(const uint4*)&g_kl[src];
    }
    __syncthreads();

    const int arow   = lane & 15;
    const int akhalf = (lane >> 4) * 8;
    const int brow   = lane & 7;
    const int bkhalf = ((lane >> 3) & 1) * 8;

    float C[2][4][4] = {};

    #pragma unroll
    for (int ks = 0; ks < 4; ks++) {
        uint32_t ah[2][4], al[2][4];
        #pragma unroll
        for (int s = 0; s < 2; s++) {
            uint32_t aaddr = sb + SC_QH + (j0w + s * 16 + arow) * 144 +
                             (ks * 16 + akhalf) * 2;
            ldsm4(ah[s], aaddr);
            ldsm4(al[s], aaddr + (SC_QL - SC_QH));
        }
        #pragma unroll
        for (int nc = 0; nc < 4; nc++) {
            uint32_t baddr = sb + SC_KH + (i0w + nc * 8 + brow) * 144 +
                             (ks * 16 + bkhalf) * 2;
            uint32_t bh[2], bl[2];
            ldsm2(bh, baddr);
            ldsm2(bl, baddr + (SC_KL - SC_KH));
            #pragma unroll
            for (int s = 0; s < 2; s++) {
                mma_bf16(C[s][nc], ah[s], bh);
                mma_bf16(C[s][nc], ah[s], bl);
                mma_bf16(C[s][nc], al[s], bh);
            }
        }
    }

    float* sbm = g_s + (size_t)b * NN * NN;
    const int grp = lane >> 2, q4 = lane & 3;
    #pragma unroll
    for (int s = 0; s < 2; s++) {
        int jlo = j0 + j0w + s * 16 + grp;
        int jhi = jlo + 8;
        #pragma unroll
        for (int nc = 0; nc < 4; nc++) {
            int ii = i0 + i0w + nc * 8 + q4 * 2;
            float v00 = C[s][nc][0], v01 = C[s][nc][1];
            float v10 = C[s][nc][2], v11 = C[s][nc][3];
            float2 o0, o1;
            o0.x = (ii     >= jlo && v00 != 0.0f) ? v00 * SCALE : -CUDART_INF_F;
            o0.y = (ii + 1 >= jlo && v01 != 0.0f) ? v01 * SCALE : -CUDART_INF_F;
            o1.x = (ii     >= jhi && v10 != 0.0f) ? v10 * SCALE : -CUDART_INF_F;
            o1.y = (ii + 1 >= jhi && v11 != 0.0f) ? v11 * SCALE : -CUDART_INF_F;
            *(float2*)&sbm[(size_t)jlo * NN + ii] = o0;
            *(float2*)&sbm[(size_t)jhi * NN + ii] = o1;
        }
    }
}

// ---------------------------------------------------------------------------
// K3: row softmax over i; writes attn as bf16 hi/lo (split done here).
// ---------------------------------------------------------------------------
__global__ void softmax_kernel() {
    const int row = blockIdx.x;
    const int b = row >> 11;
    const int j = row & (NN - 1);
    const size_t rbase = (size_t)b * NN * NN + (size_t)j * NN;
    const float* srow = g_s + rbase;

    const int tid = threadIdx.x;
    float vals[8];
    float m = -CUDART_INF_F;

    #pragma unroll
    for (int l = 0; l < 8; l++) {
        int ii = tid + l * 256;
        float v = (ii >= j) ? srow[ii] : -CUDART_INF_F;
        vals[l] = v;
        m = fmaxf(m, v);
    }

    __shared__ float red[8];
    #pragma unroll
    for (int o = 16; o > 0; o >>= 1) m = fmaxf(m, __shfl_xor_sync(0xffffffffu, m, o));
    if ((tid & 31) == 0) red[tid >> 5] = m;
    __syncthreads();
    float mt = red[0];
    #pragma unroll
    for (int w = 1; w < 8; w++) mt = fmaxf(mt, red[w]);

    float sum = 0.0f;
    #pragma unroll
    for (int l = 0; l < 8; l++) {
        float e = __expf(vals[l] - mt);
        vals[l] = e;
        sum += e;
    }
    #pragma unroll
    for (int o = 16; o > 0; o >>= 1) sum += __shfl_xor_sync(0xffffffffu, sum, o);
    __syncthreads();
    if ((tid & 31) == 0) red[tid >> 5] = sum;
    __syncthreads();
    float st = 0.0f;
    #pragma unroll
    for (int w = 0; w < 8; w++) st += red[w];

    float inv = 1.0f / st;
    #pragma unroll
    for (int l = 0; l < 8; l++) {
        int ii = tid + l * 256;
        float a = vals[l] * inv;
        float h = bhi(a);
        g_ah[rbase + ii] = __float2bfloat16_rn(h);
        g_al[rbase + ii] = __float2bfloat16_rn(a - h);
    }
}

// ---------------------------------------------------------------------------
// K4: out[b,i,h] = sum_j attn[b,j,i] * v[b,j,h]  (transposed application).
// Split-K over j, atomicAdd into out. grid (72, B). Pure-copy fills.
// ---------------------------------------------------------------------------
#define OT_AH 0                  /* 64 x 272B = 17408 */
#define OT_AL 17408
#define OT_VH 34816              /* 64 x 144B = 9216 */
#define OT_VL 44032
#define OT_SMEM 53248

__global__ __launch_bounds__(256, 2)
void out_kernel(float* __restrict__ out) {
    int c = blockIdx.x, it = 0;
    for (;;) { int f = (it >> 1) + 1; if (c < f) break; c -= f; it++; }
    const int b = blockIdx.y;
    const int i0 = it * 128;
    const int jbeg = c * 256;
    const int jend = min(jbeg + 256, (it + 1) * 128);

    extern __shared__ char sm[];
    const uint32_t sb = smem_u32(sm);
    const int tid = threadIdx.x;
    const int wid = tid >> 5, lane = tid & 31;
    const int wi = wid >> 1, wh = wid & 1;
    const int i0w = wi * 32, h0w = wh * 32;

    const size_t aoff = (size_t)b * NN * NN;
    const size_t voff = (size_t)b * NN * HH;

    const int atr = ((lane >> 4) & 1) * 8 + (lane & 7);
    const int atc = ((lane >> 3) & 1) * 8;
    const int btr = ((lane >> 3) & 1) * 8 + (lane & 7);

    float C[2][4][4] = {};

    for (int j0 = jbeg; j0 < jend; j0 += 64) {
        // attn tile 64j x 128i: 1024 uint4 per array
        #pragma unroll
        for (int l = 0; l < 4; l++) {
            int idx = tid + l * 256;
            int r = idx >> 4, cc = idx & 15;
            size_t src = aoff + (size_t)(j0 + r) * NN + i0 + cc * 8;
            int off = r * 272 + cc * 16;
            *(uint4*)(sm + OT_AH + off) = *(const uint4*)&g_ah[src];
            *(uint4*)(sm + OT_AL + off) = *(const uint4*)&g_al[src];
        }
        // v tile 64j x 64h: 512 uint4 per array
        #pragma unroll
        for (int l = 0; l < 2; l++) {
            int idx = tid + l * 256;
            int r = idx >> 3, cc = idx & 7;
            size_t src = voff + (size_t)(j0 + r) * HH + cc * 8;
            int off = r * 144 + cc * 16;
            *(uint4*)(sm + OT_VH + off) = *(const uint4*)&g_vh[src];
            *(uint4*)(sm + OT_VL + off) = *(const uint4*)&g_vl[src];
        }
        __syncthreads();

        #pragma unroll
        for (int ks = 0; ks < 4; ks++) {
            uint32_t ah[2][4], al[2][4];
            #pragma unroll
            for (int s = 0; s < 2; s++) {
                uint32_t aaddr = sb + OT_AH + (ks * 16 + atr) * 272 +
                                 (i0w + s * 16 + atc) * 2;
                ldsm4t(ah[s], aaddr);
                ldsm4t(al[s], aaddr + (OT_AL - OT_AH));
            }
            #pragma unroll
            for (int nc = 0; nc < 4; nc++) {
                uint32_t baddr = sb + OT_VH + (ks * 16 + btr) * 144 +
                                 (h0w + nc * 8) * 2;
                uint32_t bh[2], bl[2];
                ldsm2t(bh, baddr);
                ldsm2t(bl, baddr + (OT_VL - OT_VH));
                #pragma unroll
                for (int s = 0; s < 2; s++) {
                    mma_bf16(C[s][nc], ah[s], bh);
                    mma_bf16(C[s][nc], ah[s], bl);
                    mma_bf16(C[s][nc], al[s], bh);
                }
            }
        }
        __syncthreads();
    }

    const int grp = lane >> 2, q4 = lane & 3;
    #pragma unroll
    for (int s = 0; s < 2; s++) {
        int rlo = i0 + i0w + s * 16 + grp;
        int rhi = rlo + 8;
        #pragma unroll
        for (int nc = 0; nc < 4; nc++) {
            int hcol = h0w + nc * 8 + q4 * 2;
            float* p0 = &out[(size_t)b * NN * HH + (size_t)rlo * HH + hcol];
            float* p1 = &out[(size_t)b * NN * HH + (size_t)rhi * HH + hcol];
            atomicAdd(p0,     C[s][nc][0]);
            atomicAdd(p0 + 1, C[s][nc][1]);
            atomicAdd(p1,     C[s][nc][2]);
            atomicAdd(p1 + 1, C[s][nc][3]);
        }
    }
}

// ---------------------------------------------------------------------------
extern "C" void kernel_launch(void* const* d_in, const int* in_sizes, int n_in,
                              void* d_out, int out_size) {
    const float* x  = (const float*)d_in[0];
    const float* Wq = (const float*)d_in[1];
    const float* bq = (const float*)d_in[2];
    const float* Wk = (const float*)d_in[3];
    const float* bk = (const float*)d_in[4];
    const float* Wv = (const float*)d_in[5];
    const float* bv = (const float*)d_in[6];
    float* out = (float*)d_out;

    cudaFuncSetAttribute(qkv_kernel,
                         cudaFuncAttributeMaxDynamicSharedMemorySize, QKV_SMEM);
    cudaFuncSetAttribute(scores_kernel,
                         cudaFuncAttributeMaxDynamicSharedMemorySize, SC_SMEM);
    cudaFuncSetAttribute(out_kernel,
                         cudaFuncAttributeMaxDynamicSharedMemorySize, OT_SMEM);

    prep_kernel<<<8192, 256>>>(x, Wq, Wk, Wv, out);

    dim3 g1((BB * NN) / 128, 3);
    qkv_kernel<<<g1, 256, QKV_SMEM>>>(bq, bk, bv);

    dim3 g2(NN / 64, NN / 128, BB);   // (32,16,4), culled by it<2*jt
    scores_kernel<<<g2, 256, SC_SMEM>>>();

    softmax_kernel<<<BB * NN, 256>>>();

    dim3 g4(72, BB);
    out_kernel<<<g4, 256, OT_SMEM>>>(out);
}